// round 1
// baseline (speedup 1.0000x reference)
#include <cuda_runtime.h>

// Problem constants (fixed by setup_inputs)
#define V_N     500000
#define NF_N    1000000
#define KDEG    7
#define NREP    4

#define NV3     (3*V_N)            // 1,500,000
#define NF3     (3*NF_N)           // 3,000,000
#define FACES_OUT_BASE  (NREP*NV3) // 6,000,000
#define SCALAR_BASE     (FACES_OUT_BASE + NREP*NF3) // 18,000,000

// ---------------------------------------------------------------------------
// Kernel 1: vertices_rep (4 copies of vertices+center) + zero the 4 scalar
// output slots (loss accumulators + the two literal zeros).
// ---------------------------------------------------------------------------
__global__ void rep_verts_kernel(const float* __restrict__ vertices,
                                 const float* __restrict__ center,
                                 float* __restrict__ out) {
    int i = blockIdx.x * blockDim.x + threadIdx.x;
    if (i < 4) out[SCALAR_BASE + i] = 0.0f;

    const float c0 = center[0], c1 = center[1], c2 = center[2];
    int stride = gridDim.x * blockDim.x;
    for (int idx = i; idx < NV3; idx += stride) {
        int m = idx % 3;
        float c = (m == 0) ? c0 : (m == 1 ? c1 : c2);
        float v = vertices[idx] + c;
        out[idx]           = v;
        out[idx +   NV3]   = v;
        out[idx + 2*NV3]   = v;
        out[idx + 3*NV3]   = v;
    }
}

// ---------------------------------------------------------------------------
// Kernel 2: faces_rep (4 copies, int32 -> float32)
// ---------------------------------------------------------------------------
__global__ void rep_faces_kernel(const int* __restrict__ faces,
                                 float* __restrict__ out) {
    int i = blockIdx.x * blockDim.x + threadIdx.x;
    int stride = gridDim.x * blockDim.x;
    float* fo = out + FACES_OUT_BASE;
    for (int idx = i; idx < NF3; idx += stride) {
        float f = (float)faces[idx];
        fo[idx]           = f;
        fo[idx +   NF3]   = f;
        fo[idx + 2*NF3]   = f;
        fo[idx + 3*NF3]   = f;
    }
}

// ---------------------------------------------------------------------------
// Kernel 3: per-vertex fused losses.
//   k SpMV: row v owns entries [7v, 7v+7)  (k_rows = repeat(arange(V), 7))
//   lap SpMV: off-diagonal entries are sorted by row in lap_rows[0..nnz_e);
//             trailing V entries are the diagonal (val=-1, col=v).
//   laplacian_loss = mean_v ||lap_out[v]||_2
//   hexagon_loss   = mean_v <k_out[v], k_out[v]>
// ---------------------------------------------------------------------------
__global__ void loss_kernel(const float* __restrict__ vertices,
                            const float* __restrict__ center,
                            const int*   __restrict__ lap_rows,
                            const int*   __restrict__ lap_cols,
                            const float* __restrict__ lap_vals,
                            const int*   __restrict__ k_cols,
                            const float* __restrict__ k_vals,
                            int nnz_e,
                            float* __restrict__ out) {
    const int v = blockIdx.x * blockDim.x + threadIdx.x;
    const float c0 = center[0], c1 = center[1], c2 = center[2];

    float lap_c = 0.0f, hex_c = 0.0f;
    if (v < V_N) {
        // ---- k SpMV (CSR-implicit, 7 entries per row) ----
        float ax = 0.f, ay = 0.f, az = 0.f;
        const int kb = v * KDEG;
        #pragma unroll
        for (int j = 0; j < KDEG; ++j) {
            int   c = k_cols[kb + j];
            float w = k_vals[kb + j];
            ax += w * (vertices[3*c]     + c0);
            ay += w * (vertices[3*c + 1] + c1);
            az += w * (vertices[3*c + 2] + c2);
        }
        hex_c = ax*ax + ay*ay + az*az;

        // ---- lap SpMV: binary search row segment in sorted prefix ----
        int lo = 0, hi = nnz_e;
        while (lo < hi) {
            int mid = (lo + hi) >> 1;
            if (lap_rows[mid] < v) lo = mid + 1; else hi = mid;
        }
        // diagonal term: -1 * verts[v]
        float sx = -(vertices[3*v]     + c0);
        float sy = -(vertices[3*v + 1] + c1);
        float sz = -(vertices[3*v + 2] + c2);
        for (int j = lo; j < nnz_e && lap_rows[j] == v; ++j) {
            int   c = lap_cols[j];
            float w = lap_vals[j];
            sx += w * (vertices[3*c]     + c0);
            sy += w * (vertices[3*c + 1] + c1);
            sz += w * (vertices[3*c + 2] + c2);
        }
        lap_c = sqrtf(sx*sx + sy*sy + sz*sz);
    }

    // ---- block reduction (warp shuffle + shared) ----
    const unsigned FULL = 0xFFFFFFFFu;
    #pragma unroll
    for (int off = 16; off > 0; off >>= 1) {
        lap_c += __shfl_down_sync(FULL, lap_c, off);
        hex_c += __shfl_down_sync(FULL, hex_c, off);
    }
    __shared__ float s_lap[8];
    __shared__ float s_hex[8];
    int lane = threadIdx.x & 31;
    int wid  = threadIdx.x >> 5;
    if (lane == 0) { s_lap[wid] = lap_c; s_hex[wid] = hex_c; }
    __syncthreads();
    if (wid == 0) {
        int nwarp = blockDim.x >> 5;
        float l = (lane < nwarp) ? s_lap[lane] : 0.f;
        float h = (lane < nwarp) ? s_hex[lane] : 0.f;
        #pragma unroll
        for (int off = 4; off > 0; off >>= 1) {
            l += __shfl_down_sync(FULL, l, off);
            h += __shfl_down_sync(FULL, h, off);
        }
        if (lane == 0) {
            const float inv = 1.0f / (float)V_N;
            atomicAdd(out + SCALAR_BASE,     l * inv);
            atomicAdd(out + SCALAR_BASE + 1, h * inv);
        }
    }
}

// ---------------------------------------------------------------------------
// Launch. Inputs (metadata order):
//   0 vertices (1.5M f32), 1 center (3 f32), 2 lap_rows, 3 lap_cols,
//   4 lap_vals, 5 k_rows, 6 k_cols, 7 k_vals, 8 faces (3M i32), 9 total_num
// ---------------------------------------------------------------------------
extern "C" void kernel_launch(void* const* d_in, const int* in_sizes, int n_in,
                              void* d_out, int out_size) {
    const float* vertices = (const float*)d_in[0];
    const float* center   = (const float*)d_in[1];
    const int*   lap_rows = (const int*)  d_in[2];
    const int*   lap_cols = (const int*)  d_in[3];
    const float* lap_vals = (const float*)d_in[4];
    const int*   k_cols   = (const int*)  d_in[6];
    const float* k_vals   = (const float*)d_in[7];
    const int*   faces    = (const int*)  d_in[8];
    float* out = (float*)d_out;

    const int nnz_e = in_sizes[2] - V_N;  // off-diagonal (sorted) entry count

    // Kernel 1 zeros the scalar slots; kernel 3 atomically accumulates into
    // them. Same stream => ordered.
    rep_verts_kernel<<<2048, 256>>>(vertices, center, out);
    rep_faces_kernel<<<4096, 256>>>(faces, out);
    loss_kernel<<<(V_N + 255) / 256, 256>>>(vertices, center,
                                            lap_rows, lap_cols, lap_vals,
                                            k_cols, k_vals, nnz_e, out);
}

// round 2
// speedup vs baseline: 1.1098x; 1.1098x over previous
#include <cuda_runtime.h>

// Problem constants (fixed by setup_inputs)
#define V_N     500000
#define NF_N    1000000
#define KDEG    7
#define NREP    4

#define NV3     (3*V_N)            // 1,500,000 floats
#define NF3     (3*NF_N)           // 3,000,000 floats
#define FACES_OUT_BASE  (NREP*NV3) // 6,000,000
#define SCALAR_BASE     (FACES_OUT_BASE + NREP*NF3) // 18,000,000

#define NV4     (NV3/4)            // 375,000 float4
#define NF4     (NF3/4)            // 750,000 int4

// CSR row starts for the lap off-diagonal block (scratch, rebuilt every call)
__device__ int g_row_start[V_N + 1];

// ---------------------------------------------------------------------------
// Kernel 0: build row_ptr from sorted lap_rows. One thread per entry (+1 tail).
// ---------------------------------------------------------------------------
__global__ void build_rowptr_kernel(const int* __restrict__ lap_rows, int nnz_e) {
    int j = blockIdx.x * blockDim.x + threadIdx.x;
    if (j > nnz_e) return;
    if (j == nnz_e) {
        int last = (nnz_e > 0) ? lap_rows[nnz_e - 1] : -1;
        for (int r = last + 1; r <= V_N; ++r) g_row_start[r] = nnz_e;
        return;
    }
    int r  = lap_rows[j];
    int rp = (j == 0) ? -1 : lap_rows[j - 1];
    for (int r2 = rp + 1; r2 <= r; ++r2) g_row_start[r2] = j;
}

// ---------------------------------------------------------------------------
// Kernel 1: vertices_rep, vectorized float4. Also zeros the 4 scalar slots.
// ---------------------------------------------------------------------------
__global__ void rep_verts_kernel(const float4* __restrict__ vertices4,
                                 const float*  __restrict__ center,
                                 float4* __restrict__ out4) {
    int i = blockIdx.x * blockDim.x + threadIdx.x;
    if (i < 1) {  // zero the scalar slots (out4 elem SCALAR_BASE/4 = scalar block)
        float4 z = make_float4(0.f, 0.f, 0.f, 0.f);
        out4[SCALAR_BASE / 4] = z;
    }
    if (i >= NV4) return;

    float cc[6];
    cc[0] = center[0]; cc[1] = center[1]; cc[2] = center[2];
    cc[3] = cc[0]; cc[4] = cc[1]; cc[5] = cc[2];

    int b = i % 3;                 // (4*i) mod 3 == i mod 3
    float4 v = vertices4[i];
    v.x += cc[b];
    v.y += cc[b + 1];
    v.z += cc[b + 2];
    v.w += cc[b];                  // (4*i+3) mod 3 == i mod 3
    out4[i]            = v;
    out4[i +   NV4]    = v;
    out4[i + 2*NV4]    = v;
    out4[i + 3*NV4]    = v;
}

// ---------------------------------------------------------------------------
// Kernel 2: faces_rep, vectorized int4 -> float4, 4 copies.
// ---------------------------------------------------------------------------
__global__ void rep_faces_kernel(const int4* __restrict__ faces4,
                                 float4* __restrict__ out4) {
    int i = blockIdx.x * blockDim.x + threadIdx.x;
    if (i >= NF4) return;
    int4 f = faces4[i];
    float4 v = make_float4((float)f.x, (float)f.y, (float)f.z, (float)f.w);
    float4* fo = out4 + FACES_OUT_BASE / 4;
    fo[i]           = v;
    fo[i +   NF4]   = v;
    fo[i + 2*NF4]   = v;
    fo[i + 3*NF4]   = v;
}

// ---------------------------------------------------------------------------
// Kernel 3: per-vertex fused losses, CSR with precomputed row_ptr.
// ---------------------------------------------------------------------------
__global__ void loss_kernel(const float* __restrict__ vertices,
                            const float* __restrict__ center,
                            const int*   __restrict__ lap_cols,
                            const float* __restrict__ lap_vals,
                            const int*   __restrict__ k_cols,
                            const float* __restrict__ k_vals,
                            float* __restrict__ out) {
    const int v = blockIdx.x * blockDim.x + threadIdx.x;
    const float c0 = center[0], c1 = center[1], c2 = center[2];

    float lap_c = 0.0f, hex_c = 0.0f;
    if (v < V_N) {
        // ---- k SpMV (7 entries per row, independent gathers) ----
        float ax = 0.f, ay = 0.f, az = 0.f;
        const int kb = v * KDEG;
        #pragma unroll
        for (int j = 0; j < KDEG; ++j) {
            int   c = __ldg(&k_cols[kb + j]);
            float w = __ldg(&k_vals[kb + j]);
            ax += w * (vertices[3*c]     + c0);
            ay += w * (vertices[3*c + 1] + c1);
            az += w * (vertices[3*c + 2] + c2);
        }
        hex_c = ax*ax + ay*ay + az*az;

        // ---- lap SpMV: known trip count from row_ptr ----
        const int s = g_row_start[v];
        const int e = g_row_start[v + 1];
        float sx = -(vertices[3*v]     + c0);
        float sy = -(vertices[3*v + 1] + c1);
        float sz = -(vertices[3*v + 2] + c2);
        #pragma unroll 4
        for (int j = s; j < e; ++j) {
            int   c = __ldg(&lap_cols[j]);
            float w = __ldg(&lap_vals[j]);
            sx += w * (vertices[3*c]     + c0);
            sy += w * (vertices[3*c + 1] + c1);
            sz += w * (vertices[3*c + 2] + c2);
        }
        lap_c = sqrtf(sx*sx + sy*sy + sz*sz);
    }

    // ---- block reduction ----
    const unsigned FULL = 0xFFFFFFFFu;
    #pragma unroll
    for (int off = 16; off > 0; off >>= 1) {
        lap_c += __shfl_down_sync(FULL, lap_c, off);
        hex_c += __shfl_down_sync(FULL, hex_c, off);
    }
    __shared__ float s_lap[8];
    __shared__ float s_hex[8];
    int lane = threadIdx.x & 31;
    int wid  = threadIdx.x >> 5;
    if (lane == 0) { s_lap[wid] = lap_c; s_hex[wid] = hex_c; }
    __syncthreads();
    if (wid == 0) {
        int nwarp = blockDim.x >> 5;
        float l = (lane < nwarp) ? s_lap[lane] : 0.f;
        float h = (lane < nwarp) ? s_hex[lane] : 0.f;
        #pragma unroll
        for (int off = 4; off > 0; off >>= 1) {
            l += __shfl_down_sync(FULL, l, off);
            h += __shfl_down_sync(FULL, h, off);
        }
        if (lane == 0) {
            const float inv = 1.0f / (float)V_N;
            atomicAdd(out + SCALAR_BASE,     l * inv);
            atomicAdd(out + SCALAR_BASE + 1, h * inv);
        }
    }
}

// ---------------------------------------------------------------------------
// Launch. Inputs (metadata order):
//   0 vertices, 1 center, 2 lap_rows, 3 lap_cols, 4 lap_vals,
//   5 k_rows, 6 k_cols, 7 k_vals, 8 faces, 9 total_num
// ---------------------------------------------------------------------------
extern "C" void kernel_launch(void* const* d_in, const int* in_sizes, int n_in,
                              void* d_out, int out_size) {
    const float* vertices = (const float*)d_in[0];
    const float* center   = (const float*)d_in[1];
    const int*   lap_rows = (const int*)  d_in[2];
    const int*   lap_cols = (const int*)  d_in[3];
    const float* lap_vals = (const float*)d_in[4];
    const int*   k_cols   = (const int*)  d_in[6];
    const float* k_vals   = (const float*)d_in[7];
    const int*   faces    = (const int*)  d_in[8];
    float* out = (float*)d_out;

    const int nnz_e = in_sizes[2] - V_N;  // off-diagonal (sorted) entry count

    build_rowptr_kernel<<<(nnz_e + 1 + 255) / 256, 256>>>(lap_rows, nnz_e);
    rep_verts_kernel<<<(NV4 + 255) / 256, 256>>>((const float4*)vertices, center,
                                                 (float4*)out);
    rep_faces_kernel<<<(NF4 + 255) / 256, 256>>>((const int4*)faces, (float4*)out);
    loss_kernel<<<(V_N + 255) / 256, 256>>>(vertices, center,
                                            lap_cols, lap_vals,
                                            k_cols, k_vals, out);
}